// round 11
// baseline (speedup 1.0000x reference)
#include <cuda_runtime.h>
#include <math.h>

// Problem dims
#define SDIM 256
#define BDIM 64
#define EDIM 1024
#define VDIM 5

#define NCTA 128
#define NTHR 256

// ---------------- scratch (device globals; no allocs allowed) ----------------
#define KT_OFF   0
#define VT_OFF   16777216
#define H1_OFF   33554432
#define C1_OFF   (H1_OFF + 65536)
#define H2_OFF   (C1_OFF + 65536)
#define C2_OFF   (H2_OFF + 65536)
#define QP_OFF   (C2_OFF + 65536)
#define WOP_OFF  (QP_OFF + 524288)
#define CTX_OFF  (WOP_OFF + 524288)
#define ATT_OFF  (CTX_OFF + 65536)
#define G1_OFF   (ATT_OFF + 65536)
#define G2_OFF   (G1_OFF + 524288)
#define BUF_TOTAL (G2_OFF + 524288)

__device__ float g_buf[BUF_TOTAL];
__device__ unsigned g_bar_cnt = 0;
__device__ unsigned g_bar_gen = 0;

// ---------------- f32x2 packed-FMA helpers ----------------
__device__ __forceinline__ unsigned long long pk2(float lo, float hi) {
    unsigned long long r;
    asm("mov.b64 %0, {%1,%2};" : "=l"(r) : "f"(lo), "f"(hi));
    return r;
}
__device__ __forceinline__ void fma2(unsigned long long &d, unsigned long long a, unsigned long long b) {
    asm("fma.rn.f32x2 %0, %1, %2, %0;" : "+l"(d) : "l"(a), "l"(b));
}
__device__ __forceinline__ float2 upk2(unsigned long long v) {
    float lo, hi;
    asm("mov.b64 {%0,%1}, %2;" : "=f"(lo), "=f"(hi) : "l"(v));
    return make_float2(lo, hi);
}
__device__ __forceinline__ float sigf(float x) { return 1.f / (1.f + expf(-x)); }

// ---------------- grid barrier (all 128 CTAs co-resident) ----------------
__device__ __forceinline__ void grid_bar() {
    __threadfence();          // every thread's g_buf stores -> visible at L2
    __syncthreads();
    if (threadIdx.x == 0) {
        volatile unsigned* vg = &g_bar_gen;
        unsigned gen = *vg;
        if (atomicAdd(&g_bar_cnt, 1u) == NCTA - 1u) {
            g_bar_cnt = 0u;
            __threadfence();
            *vg = gen + 1u;
        } else {
            while (*vg == gen) { __nanosleep(64); }
        }
    }
    __syncthreads();
}

// ---------------- K/V precompute GEMM (separate launch; unchanged, validated) ----------------
__global__ __launch_bounds__(256) void gemm_kv(const float* __restrict__ cnn,
                                               const float* __restrict__ w_qkv,
                                               const float* __restrict__ b_qkv) {
    __shared__ float As[16 * 68];
    __shared__ float Ws[16 * 68];
    int tid = threadIdx.x;
    int ty = tid >> 4, tx = tid & 15;
    int lr = tid >> 2, lk = (tid & 3) << 2;
    int n0 = blockIdx.x << 6;
    int m0 = blockIdx.y << 6;

    const float* Arow = cnn + (size_t)(m0 + lr) * EDIM + lk;
    const float* Wrow = w_qkv + (size_t)(EDIM + n0 + lr) * EDIM + lk;

    unsigned long long a00=0,a01=0,a10=0,a11=0,a20=0,a21=0,a30=0,a31=0;

    float4 av = *(const float4*)(Arow);
    float4 wv = *(const float4*)(Wrow);
    for (int kt = 0; kt < EDIM; kt += 16) {
        __syncthreads();
        As[(lk)*68+lr]=av.x; As[(lk+1)*68+lr]=av.y; As[(lk+2)*68+lr]=av.z; As[(lk+3)*68+lr]=av.w;
        Ws[(lk)*68+lr]=wv.x; Ws[(lk+1)*68+lr]=wv.y; Ws[(lk+2)*68+lr]=wv.z; Ws[(lk+3)*68+lr]=wv.w;
        __syncthreads();
        if (kt + 16 < EDIM) {
            av = *(const float4*)(Arow + kt + 16);
            wv = *(const float4*)(Wrow + kt + 16);
        }
#pragma unroll
        for (int k = 0; k < 16; k++) {
            float4 a = *(const float4*)&As[k*68 + (ty<<2)];
            float4 w = *(const float4*)&Ws[k*68 + (tx<<2)];
            unsigned long long w01 = pk2(w.x, w.y), w23 = pk2(w.z, w.w), ad;
            ad = pk2(a.x, a.x); fma2(a00, ad, w01); fma2(a01, ad, w23);
            ad = pk2(a.y, a.y); fma2(a10, ad, w01); fma2(a11, ad, w23);
            ad = pk2(a.z, a.z); fma2(a20, ad, w01); fma2(a21, ad, w23);
            ad = pk2(a.w, a.w); fma2(a30, ad, w01); fma2(a31, ad, w23);
        }
    }
    unsigned long long accs[4][2] = {{a00,a01},{a10,a11},{a20,a21},{a30,a31}};
#pragma unroll
    for (int i = 0; i < 4; i++) {
        int mg = m0 + (ty << 2) + i;
        int s = mg >> 6, b = mg & 63;
        float2 p0 = upk2(accs[i][0]), p1 = upk2(accs[i][1]);
        float vals[4] = {p0.x, p0.y, p1.x, p1.y};
#pragma unroll
        for (int j = 0; j < 4; j++) {
            int n = n0 + (tx << 2) + j;
            float v = vals[j] + b_qkv[EDIM + n];
            if (n < EDIM) {
                int h = n >> 8, d = n & 255;
                g_buf[KT_OFF + (((b << 2) + h) * 256 + d) * 256 + s] = v;
            } else {
                int n2 = n - EDIM;
                int h = n2 >> 8, d = n2 & 255;
                g_buf[VT_OFF + (((b << 2) + h) * 256 + s) * 256 + d] = v;
            }
        }
    }
}

// ---------------- per-step GEMM (M=64), register-prefetch pipelined ----------------
// Cross-CTA A operands read via __ldcg (L2) — L1 may be stale across steps.
__device__ __noinline__ void gemm64(
    const float* __restrict__ W0, const float* __restrict__ W1, const float* __restrict__ W2,
    int a0, int a1, int a2,
    int ldw0, int ldw1, int ldw2,
    int N, int Kper, int outOff, int bx, int by, float* sh)
{
    float* As = sh;
    float* Ws = sh + 16 * 68;
    int tid = threadIdx.x;
    int ty = tid >> 4, tx = tid & 15;
    int lr = tid >> 2, lk = (tid & 3) << 2;
    int n0 = bx << 6;
    int k0 = by * Kper;

    unsigned long long a00=0,a01=0,a10=0,a11=0,a20=0,a21=0,a30=0,a31=0;

    // prefetch first tile
    float4 av, wv;
    {
        int seg = k0 >> 10, kin = k0 & 1023;
        int ab = (seg == 0 ? a0 : (seg == 1 ? a1 : a2));
        const float* Wb = (seg == 0 ? W0 : (seg == 1 ? W1 : W2));
        int ldw = (seg == 0 ? ldw0 : (seg == 1 ? ldw1 : ldw2));
        av = __ldcg((const float4*)(g_buf + ab + lr * EDIM + kin + lk));
        wv = *(const float4*)(Wb + (size_t)(n0 + lr) * ldw + kin + lk);
    }

    for (int kt = k0; kt < k0 + Kper; kt += 16) {
        __syncthreads();
        As[(lk)*68+lr]=av.x; As[(lk+1)*68+lr]=av.y; As[(lk+2)*68+lr]=av.z; As[(lk+3)*68+lr]=av.w;
        Ws[(lk)*68+lr]=wv.x; Ws[(lk+1)*68+lr]=wv.y; Ws[(lk+2)*68+lr]=wv.z; Ws[(lk+3)*68+lr]=wv.w;
        __syncthreads();
        int kn = kt + 16;
        if (kn < k0 + Kper) {   // prefetch next tile while computing this one
            int seg = kn >> 10, kin = kn & 1023;
            int ab = (seg == 0 ? a0 : (seg == 1 ? a1 : a2));
            const float* Wb = (seg == 0 ? W0 : (seg == 1 ? W1 : W2));
            int ldw = (seg == 0 ? ldw0 : (seg == 1 ? ldw1 : ldw2));
            av = __ldcg((const float4*)(g_buf + ab + lr * EDIM + kin + lk));
            wv = *(const float4*)(Wb + (size_t)(n0 + lr) * ldw + kin + lk);
        }
#pragma unroll
        for (int k = 0; k < 16; k++) {
            float4 a = *(const float4*)&As[k*68 + (ty<<2)];
            float4 w = *(const float4*)&Ws[k*68 + (tx<<2)];
            unsigned long long w01 = pk2(w.x, w.y), w23 = pk2(w.z, w.w), ad;
            ad = pk2(a.x, a.x); fma2(a00, ad, w01); fma2(a01, ad, w23);
            ad = pk2(a.y, a.y); fma2(a10, ad, w01); fma2(a11, ad, w23);
            ad = pk2(a.z, a.z); fma2(a20, ad, w01); fma2(a21, ad, w23);
            ad = pk2(a.w, a.w); fma2(a30, ad, w01); fma2(a31, ad, w23);
        }
    }
    float* op = g_buf + outOff + (size_t)(by << 6) * N + n0 + (tx << 2);
    float2 p0, p1;
    p0 = upk2(a00); p1 = upk2(a01); *(float4*)(op + (size_t)((ty<<2)+0)*N) = make_float4(p0.x,p0.y,p1.x,p1.y);
    p0 = upk2(a10); p1 = upk2(a11); *(float4*)(op + (size_t)((ty<<2)+1)*N) = make_float4(p0.x,p0.y,p1.x,p1.y);
    p0 = upk2(a20); p1 = upk2(a21); *(float4*)(op + (size_t)((ty<<2)+2)*N) = make_float4(p0.x,p0.y,p1.x,p1.y);
    p0 = upk2(a30); p1 = upk2(a31); *(float4*)(op + (size_t)((ty<<2)+3)*N) = make_float4(p0.x,p0.y,p1.x,p1.y);
}

// ---------------- attention: each CTA handles 2 (b,h) pairs ----------------
__device__ __noinline__ void attn_dev(const float* __restrict__ b_qkv, float* sh) {
    float* qs  = sh;
    float* red = sh + 256;
    float* pr  = sh + 512;
    int t = threadIdx.x;
    for (int i = 0; i < 2; i++) {
        int bh = (blockIdx.x << 1) + i;   // 0..255
        int b = bh >> 2, h = bh & 3;
        int e = (h << 8) + t;
        float qv = b_qkv[e];
#pragma unroll
        for (int sp = 0; sp < 8; sp++) qv += __ldcg(g_buf + QP_OFF + sp * 65536 + (b << 10) + e);
        qs[t] = qv;
        __syncthreads();

        const float* Kb = g_buf + KT_OFF + bh * 65536;
        float acc = 0.f;
#pragma unroll 8
        for (int d = 0; d < 256; d++) acc += qs[d] * Kb[(d << 8) + t];
        acc *= 0.0625f;

        red[t] = acc; __syncthreads();
        for (int off = 128; off; off >>= 1) { if (t < off) red[t] = fmaxf(red[t], red[t + off]); __syncthreads(); }
        float mx = red[0]; __syncthreads();
        float ex = expf(acc - mx);
        red[t] = ex; __syncthreads();
        for (int off = 128; off; off >>= 1) { if (t < off) red[t] += red[t + off]; __syncthreads(); }
        float inv = 1.f / red[0];
        pr[t] = ex * inv;
        __syncthreads();

        const float* Vb = g_buf + VT_OFF + bh * 65536;
        float c = 0.f;
#pragma unroll 8
        for (int s2 = 0; s2 < 256; s2++) c += pr[s2] * Vb[(s2 << 8) + t];
        g_buf[ATT_OFF + (b << 10) + e] = c;
        __syncthreads();
    }
}

// ---------------- w_o split-K reduce + bias ----------------
__device__ __forceinline__ void wored_dev(const float* __restrict__ b_o) {
    for (int idx = blockIdx.x * NTHR + threadIdx.x; idx < 65536; idx += NCTA * NTHR) {
        int e = idx & 1023;
        float v = b_o[e];
#pragma unroll
        for (int sp = 0; sp < 8; sp++) v += __ldcg(g_buf + WOP_OFF + sp * 65536 + idx);
        g_buf[CTX_OFF + idx] = v;
    }
}

// ---------------- LSTM cell ----------------
__device__ __noinline__ void cell_dev(int gOff, const float* __restrict__ bi, const float* __restrict__ bh,
                                      int hOff, int cOff) {
    for (int idx = blockIdx.x * NTHR + threadIdx.x; idx < 65536; idx += NCTA * NTHR) {
        int b = idx >> 10, e = idx & 1023;
        const float* g0 = g_buf + gOff + (size_t)b * 4096;
        const float* g1 = g_buf + gOff + (size_t)(64 + b) * 4096;
        float gi = __ldcg(g0 + e)        + __ldcg(g1 + e)        + bi[e]        + bh[e];
        float gf = __ldcg(g0 + 1024 + e) + __ldcg(g1 + 1024 + e) + bi[1024 + e] + bh[1024 + e];
        float gg = __ldcg(g0 + 2048 + e) + __ldcg(g1 + 2048 + e) + bi[2048 + e] + bh[2048 + e];
        float go = __ldcg(g0 + 3072 + e) + __ldcg(g1 + 3072 + e) + bi[3072 + e] + bh[3072 + e];
        float c = __ldcg(g_buf + cOff + idx);
        float cn = sigf(gf) * c + sigf(gi) * tanhf(gg);
        g_buf[cOff + idx] = cn;
        g_buf[hOff + idx] = sigf(go) * tanhf(cn);
    }
}

// ---------------- output head (CTAs 0..63, 5 warps used) ----------------
__device__ __forceinline__ void head_dev(const float* __restrict__ w_out, const float* __restrict__ b_out,
                                         float* __restrict__ out, int t) {
    if (blockIdx.x < 64 && threadIdx.x < 160) {
        int b = blockIdx.x;
        int w = threadIdx.x >> 5, lane = threadIdx.x & 31;
        const float* hb = g_buf + H2_OFF + (b << 10);
        const float* wr = w_out + w * 1024;
        float a = 0.f;
        for (int j = lane; j < 1024; j += 32) a += __ldcg(hb + j) * wr[j];
#pragma unroll
        for (int off = 16; off; off >>= 1) a += __shfl_down_sync(0xffffffffu, a, off);
        if (lane == 0) {
            a += b_out[w];
            if (w >= 2) a = 1.f / (1.f + expf(-a));
            out[((t << 6) + b) * VDIM + w] = a;
        }
    }
}

// ---------------- persistent main kernel: whole 256-step recurrence ----------------
__global__ __launch_bounds__(NTHR, 1) void main_kernel(
    const float* __restrict__ w_qkv, const float* __restrict__ b_qkv,
    const float* __restrict__ w_o,   const float* __restrict__ b_o,
    const float* __restrict__ w_ih1, const float* __restrict__ w_hh1,
    const float* __restrict__ b_ih1, const float* __restrict__ b_hh1,
    const float* __restrict__ w_ih2, const float* __restrict__ w_hh2,
    const float* __restrict__ b_ih2, const float* __restrict__ b_hh2,
    const float* __restrict__ w_out, const float* __restrict__ b_out,
    float* __restrict__ out)
{
    __shared__ float sh[2 * 16 * 68];
    int r = blockIdx.x;

    // zero recurrent state (h1,c1,h2,c2)
    for (int i = r * NTHR + threadIdx.x; i < 4 * BDIM * EDIM; i += NCTA * NTHR)
        g_buf[H1_OFF + i] = 0.f;
    grid_bar();

    for (int t = 0; t < SDIM; t++) {
        // phase 1: output head for t-1 (reads finalized h2) + q projection
        if (t > 0) head_dev(w_out, b_out, out, t - 1);
        gemm64(w_qkv, w_qkv, w_qkv, H2_OFF, H2_OFF, H2_OFF,
               EDIM, EDIM, EDIM, EDIM, 128, QP_OFF, r & 15, r >> 4, sh);
        grid_bar();
        // phase 2: attention (sums q partials + b_q)
        attn_dev(b_qkv, sh);
        grid_bar();
        // phase 3: ctx = att @ w_o^T partials
        gemm64(w_o, w_o, w_o, ATT_OFF, ATT_OFF, ATT_OFF,
               EDIM, EDIM, EDIM, EDIM, 128, WOP_OFF, r & 15, r >> 4, sh);
        grid_bar();
        // phase 4: reduce + b_o
        wored_dev(b_o);
        grid_bar();
        // phase 5: gates1 = h2@Wih1[:,:E]^T + ctx@Wih1[:,E:]^T + h1@Whh1^T
        gemm64(w_ih1, w_ih1 + 1024, w_hh1, H2_OFF, CTX_OFF, H1_OFF,
               2048, 2048, 1024, 4096, 1536, G1_OFF, r >> 1, r & 1, sh);
        grid_bar();
        // phase 6: LSTM cell 1
        cell_dev(G1_OFF, b_ih1, b_hh1, H1_OFF, C1_OFF);
        grid_bar();
        // phase 7: gates2 = h1new@Wih2^T + h2prev@Whh2^T
        gemm64(w_ih2, w_hh2, w_hh2, H1_OFF, H2_OFF, H2_OFF,
               1024, 1024, 1024, 4096, 1024, G2_OFF, r >> 1, r & 1, sh);
        grid_bar();
        // phase 8: LSTM cell 2 (writes new h2)
        cell_dev(G2_OFF, b_ih2, b_hh2, H2_OFF, C2_OFF);
        grid_bar();
    }
    // final step's head
    head_dev(w_out, b_out, out, SDIM - 1);
}

// ---------------- host ----------------
extern "C" void kernel_launch(void* const* d_in, const int* in_sizes, int n_in,
                              void* d_out, int out_size) {
    const float* cnn    = (const float*)d_in[0];
    const float* w_qkv  = (const float*)d_in[1];
    const float* b_qkv  = (const float*)d_in[2];
    const float* w_o    = (const float*)d_in[3];
    const float* b_o    = (const float*)d_in[4];
    const float* w_ih1  = (const float*)d_in[5];
    const float* w_hh1  = (const float*)d_in[6];
    const float* b_ih1  = (const float*)d_in[7];
    const float* b_hh1  = (const float*)d_in[8];
    const float* w_ih2  = (const float*)d_in[9];
    const float* w_hh2  = (const float*)d_in[10];
    const float* b_ih2  = (const float*)d_in[11];
    const float* b_hh2  = (const float*)d_in[12];
    const float* w_out  = (const float*)d_in[13];
    const float* b_out  = (const float*)d_in[14];
    float* out = (float*)d_out;

    // K/V projections into attention-friendly layouts
    gemm_kv<<<dim3(32, 256), 256>>>(cnn, w_qkv, b_qkv);

    // entire recurrence in one persistent kernel (128 co-resident CTAs)
    main_kernel<<<NCTA, NTHR>>>(w_qkv, b_qkv, w_o, b_o,
                                w_ih1, w_hh1, b_ih1, b_hh1,
                                w_ih2, w_hh2, b_ih2, b_hh2,
                                w_out, b_out, out);
}